// round 2
// baseline (speedup 1.0000x reference)
#include <cuda_runtime.h>
#include <stdint.h>

// PatchMasker: out = concat(where(mask[t], 0, x_dist),
//                           where(mask[t], 0, x_tre),
//                           where(mask[t], 0, x_sea))
// Shapes: x_* = (B=256, T=512, F=256) fp32, mask = (T=512,) int32 (bool->int32
// per harness dtype contract). Pure HBM-streaming kernel. Masked rows skip the
// input read entirely (predicated-off LDG), saving ~40% of read traffic.

#define B_DIM 256
#define T_DIM 512
#define F_DIM 256

// float4 elements per tensor: B*T*F/4
#define N4_PER ((long)B_DIM * T_DIM * F_DIM / 4)
// float4 per (b,t) row: F/4 = 64  -> t = (i4 >> 6) & (T-1)
#define ROW_SHIFT 6
#define T_MASK (T_DIM - 1)

__global__ void __launch_bounds__(256, 8)
patch_masker_kernel(const float4* __restrict__ xd,
                    const float4* __restrict__ xt,
                    const float4* __restrict__ xs,
                    const int* __restrict__ mask,
                    float4* __restrict__ out)
{
    long i = (long)blockIdx.x * blockDim.x + threadIdx.x;
    if (i >= N4_PER) return;

    int t = (int)((i >> ROW_SHIFT) & T_MASK);
    bool keep = (mask[t] == 0);   // mask is 2 KB of int32 -> lives in L1/L2

    const float4 z = make_float4(0.f, 0.f, 0.f, 0.f);

    // Predicated loads: when masked, the LDGs are predicated off and generate
    // no HBM read traffic for this row.
    float4 a = z, b = z, c = z;
    if (keep) {
        a = xd[i];
        b = xt[i];
        c = xs[i];
    }

    out[i]              = a;
    out[i +     N4_PER] = b;
    out[i + 2 * N4_PER] = c;
}

extern "C" void kernel_launch(void* const* d_in, const int* in_sizes, int n_in,
                              void* d_out, int out_size)
{
    const float4* xd = (const float4*)d_in[0];
    const float4* xt = (const float4*)d_in[1];
    const float4* xs = (const float4*)d_in[2];
    const int* mask  = (const int*)d_in[3];
    float4* out = (float4*)d_out;

    const int threads = 256;
    const long blocks = (N4_PER + threads - 1) / threads;  // 32768

    patch_masker_kernel<<<(unsigned)blocks, threads>>>(xd, xt, xs, mask, out);
}